// round 14
// baseline (speedup 1.0000x reference)
#include <cuda_runtime.h>
#include <cuda_bf16.h>
#include <math.h>

#define BATCH       32
#define HEADS       16
#define HEADDIM     128
#define BLOCK_SIZE  16
#define MAX_BLOCKS  128
#define MAX_CTX     (MAX_BLOCKS * BLOCK_SIZE)   // 2048
#define SCALE       (0.08838834764831845f)      // 1/sqrt(128)
#define NEG_BIG     (-1e30f)                    // finite -inf stand-in (no NaN arith)

#define NSPLIT      16
#define CHUNK       (MAX_CTX / NSPLIT)          // 128 tokens per split
#define NWARPS      8
#define NTHREADS    (NWARPS * 32)               // 256
#define TPS         16                          // tokens per stage == one KV block
#define NSTAGE      2                           // double buffer
#define BLOCK_ELEMS ((size_t)BLOCK_SIZE * HEADS * HEADDIM)   // floats per KV block
#define STAGE_FLOATS (NSTAGE * TPS * HEADDIM)   // 4096 floats per K (or V) ring

// Split-KV partial results: per (b, h, split)
__device__ float g_m[BATCH * HEADS * NSPLIT];
__device__ float g_s[BATCH * HEADS * NSPLIT];
__device__ float g_acc[BATCH * HEADS * NSPLIT * HEADDIM];
__device__ unsigned int g_cnt[BATCH * HEADS];   // zero-init; reset by last CTA

__device__ __forceinline__ void cp_async16(void* smem_dst, const void* gmem_src)
{
    unsigned int s = (unsigned int)__cvta_generic_to_shared(smem_dst);
    asm volatile("cp.async.cg.shared.global [%0], [%1], 16;\n" :: "r"(s), "l"(gmem_src));
}
__device__ __forceinline__ void cp_commit()
{
    asm volatile("cp.async.commit_group;\n");
}
template <int N>
__device__ __forceinline__ void cp_wait()
{
    asm volatile("cp.async.wait_group %0;\n" :: "n"(N));
}

__global__ __launch_bounds__(NTHREADS, 7)
void paged_attn_split_kernel(const float* __restrict__ query,
                             const float* __restrict__ key_cache,
                             const float* __restrict__ value_cache,
                             const int*   __restrict__ block_tables,
                             const int*   __restrict__ context_lens,
                             float*       __restrict__ out)
{
    const int h     = blockIdx.x;
    const int b     = blockIdx.y;
    const int split = blockIdx.z;
    const int tid   = threadIdx.x;
    const int lane  = tid & 31;
    const int warp  = tid >> 5;

    const int bh    = b * HEADS + h;
    const int ctx   = context_lens[b];
    const int start = split * CHUNK;

    // Inactive split: exit immediately — no partial write, no fence, no atomic.
    if (start >= ctx) return;

    const int n_active = (ctx + CHUNK - 1) / CHUNK;   // 1..NSPLIT
    const int p        = bh * NSPLIT + split;
    const int end      = min(start + CHUNK, ctx);
    const int nst      = (end - start + TPS - 1) / TPS;   // #stages (1..8)

    // 32 KB K+V ring. s_acc (4 KB) is ALIASED onto the front of the ring:
    // it is only written after the mainloop's final barrier, when stage data
    // is dead. This keeps static smem ~32.9 KB -> 7 CTAs/SM.
    __shared__ __align__(16) float s_buf[STAGE_FLOATS * 2];   // 32 KB
    __shared__ int   s_btab[CHUNK / BLOCK_SIZE];              // 8 entries
    __shared__ float s_wm[NWARPS], s_ws[NWARPS];
    __shared__ unsigned int s_ticket;

    float* const s_kb  = s_buf;                   // [NSTAGE][TPS][HEADDIM]
    float* const s_vb  = s_buf + STAGE_FLOATS;    // [NSTAGE][TPS][HEADDIM]
    float* const s_acc = s_buf;                   // [NWARPS][HEADDIM], post-loop

    if (tid < CHUNK / BLOCK_SIZE)
        s_btab[tid] = block_tables[b * MAX_BLOCKS + (start >> 4) + tid];
    __syncthreads();

    const float4 q4 =
        reinterpret_cast<const float4*>(query + (size_t)bh * HEADDIM)[lane];

    // ---- Hoisted per-thread fill constants --------------------------------
    const int    tokA  = tid >> 5;              // 0..7
    const int    tokB  = tokA + 8;              // 8..15
    const int    part4 = (tid & 31) * 4;        // float offset of 16B unit
    const size_t cA = ((size_t)tokA * HEADS + h) * HEADDIM + part4;
    const size_t cB = ((size_t)tokB * HEADS + h) * HEADDIM + part4;

    auto issue_stage = [&](int st) {
        const int    buf  = st & 1;
        const int    base = start + st * TPS;
        const size_t bb   = (size_t)s_btab[st] * BLOCK_ELEMS;  // uniform LDS
        float* kr = s_kb + (buf * TPS) * HEADDIM;
        float* vr = s_vb + (buf * TPS) * HEADDIM;
        if (base + tokA < end) {
            cp_async16(kr + (size_t)tokA * HEADDIM + part4, key_cache   + bb + cA);
            cp_async16(vr + (size_t)tokA * HEADDIM + part4, value_cache + bb + cA);
        } else {
            *reinterpret_cast<float4*>(vr + (size_t)tokA * HEADDIM + part4) =
                make_float4(0.f, 0.f, 0.f, 0.f);
        }
        if (base + tokB < end) {
            cp_async16(kr + (size_t)tokB * HEADDIM + part4, key_cache   + bb + cB);
            cp_async16(vr + (size_t)tokB * HEADDIM + part4, value_cache + bb + cB);
        } else {
            *reinterpret_cast<float4*>(vr + (size_t)tokB * HEADDIM + part4) =
                make_float4(0.f, 0.f, 0.f, 0.f);
        }
    };

    float m = NEG_BIG, s = 0.0f;
    float4 acc = make_float4(0.f, 0.f, 0.f, 0.f);

    issue_stage(0);
    cp_commit();

    for (int st = 0; st < nst; st++) {
        if (st + 1 < nst) {
            issue_stage(st + 1);
            cp_commit();
            cp_wait<1>();          // stage st complete, st+1 may be pending
        } else {
            cp_wait<0>();
        }
        __syncthreads();

        const int buf  = st & 1;
        const int t0   = start + st * TPS + warp * 2;
        const int t1   = t0 + 1;
        const float* k0p = s_kb + (buf * TPS + warp * 2) * HEADDIM;
        const float* v0p = s_vb + (buf * TPS + warp * 2) * HEADDIM;

        const float4 k0 = reinterpret_cast<const float4*>(k0p)[lane];
        const float4 k1 = reinterpret_cast<const float4*>(k0p + HEADDIM)[lane];
        const float4 v0 = reinterpret_cast<const float4*>(v0p)[lane];
        const float4 v1 = reinterpret_cast<const float4*>(v0p + HEADDIM)[lane];

        float d0 = k0.x * q4.x + k0.y * q4.y + k0.z * q4.z + k0.w * q4.w;
        float d1 = k1.x * q4.x + k1.y * q4.y + k1.z * q4.z + k1.w * q4.w;
        #pragma unroll
        for (int o2 = 16; o2; o2 >>= 1) {
            d0 += __shfl_xor_sync(0xFFFFFFFFu, d0, o2);
            d1 += __shfl_xor_sync(0xFFFFFFFFu, d1, o2);
        }
        // Finite sentinel: select kills NaN from uninit tail smem; no inf-inf.
        d0 = (t0 < end) ? d0 * SCALE : NEG_BIG;
        d1 = (t1 < end) ? d1 * SCALE : NEG_BIG;

        const float mnew = fmaxf(m, fmaxf(d0, d1));
        // Fully-idle warp: mnew==NEG_BIG, resc=p=1, but V is zeroed and the
        // merge weight exp(NEG_BIG - gm) underflows to 0 -> contributes nothing.
        const float resc = __expf(m - mnew);
        const float p0   = __expf(d0 - mnew);
        const float p1   = __expf(d1 - mnew);
        s = s * resc + p0 + p1;
        acc.x = acc.x * resc + p0 * v0.x + p1 * v1.x;
        acc.y = acc.y * resc + p0 * v0.y + p1 * v1.y;
        acc.z = acc.z * resc + p0 * v0.z + p1 * v1.z;
        acc.w = acc.w * resc + p0 * v0.w + p1 * v1.w;
        m = mnew;

        __syncthreads();           // all reads done before buffer reuse
    }

    // ---- Merge warp partials -> split partial (s_acc aliases dead stage mem;
    //      the loop's trailing __syncthreads orders last reads before writes) --
    if (lane == 0) { s_wm[warp] = m; s_ws[warp] = s; }
    reinterpret_cast<float4*>(&s_acc[warp * HEADDIM])[lane] = acc;
    __syncthreads();

    if (tid < HEADDIM) {
        float gm = NEG_BIG;
        #pragma unroll
        for (int w = 0; w < NWARPS; w++) gm = fmaxf(gm, s_wm[w]);
        float S = 0.0f, A = 0.0f;
        #pragma unroll
        for (int w = 0; w < NWARPS; w++) {
            const float wt = __expf(s_wm[w] - gm);   // idle warp: underflow -> 0
            S += wt * s_ws[w];
            A += wt * s_acc[w * HEADDIM + tid];
        }
        g_acc[(size_t)p * HEADDIM + tid] = A;
        if (tid == 0) { g_m[p] = gm; g_s[p] = S; }
    }

    // ---- Arrival ticket: last ACTIVE CTA of this (b,h) merges its splits ----
    if (tid < HEADDIM) __threadfence();   // order partial writes (writers only)
    __syncthreads();
    if (tid == 0) s_ticket = atomicAdd(&g_cnt[bh], 1u);
    __syncthreads();

    if (s_ticket == (unsigned)(n_active - 1)) {
        __threadfence();    // acquire peers' partials
        if (tid < HEADDIM) {
            float gm = NEG_BIG;
            for (int i = 0; i < n_active; i++)
                gm = fmaxf(gm, g_m[bh * NSPLIT + i]);
            float S = 0.0f, A = 0.0f;
            for (int i = 0; i < n_active; i++) {
                const float wt = __expf(g_m[bh * NSPLIT + i] - gm);
                S += wt * g_s[bh * NSPLIT + i];
                A += wt * g_acc[((size_t)bh * NSPLIT + i) * HEADDIM + tid];
            }
            out[(size_t)bh * HEADDIM + tid] = A / S;
        }
        if (tid == 0) g_cnt[bh] = 0u;   // reset for next graph replay
    }
}

extern "C" void kernel_launch(void* const* d_in, const int* in_sizes, int n_in,
                              void* d_out, int out_size)
{
    const float* query        = (const float*)d_in[0];
    const float* key_cache    = (const float*)d_in[1];
    const float* value_cache  = (const float*)d_in[2];
    const int*   block_tables = (const int*)d_in[3];
    const int*   context_lens = (const int*)d_in[4];
    float*       out          = (float*)d_out;

    dim3 grid(HEADS, BATCH, NSPLIT);
    paged_attn_split_kernel<<<grid, NTHREADS>>>(query, key_cache, value_cache,
                                                block_tables, context_lens, out);
}

// round 15
// speedup vs baseline: 1.0035x; 1.0035x over previous
#include <cuda_runtime.h>
#include <cuda_bf16.h>
#include <math.h>

#define BATCH       32
#define HEADS       16
#define HEADDIM     128
#define BLOCK_SIZE  16
#define MAX_BLOCKS  128
#define MAX_CTX     (MAX_BLOCKS * BLOCK_SIZE)   // 2048
#define SCALE       (0.08838834764831845f)      // 1/sqrt(128)
#define NEG_BIG     (-1e30f)                    // finite -inf stand-in (no NaN arith)

#define NSPLIT      32
#define CHUNK       (MAX_CTX / NSPLIT)          // 64 tokens per split
#define NWARPS      8
#define NTHREADS    (NWARPS * 32)               // 256
#define TPS         16                          // tokens per stage == one KV block
#define NSTAGE      2                           // double buffer
#define BLOCK_ELEMS ((size_t)BLOCK_SIZE * HEADS * HEADDIM)   // floats per KV block

// Split-KV partial results: per (b, h, split)
__device__ float g_m[BATCH * HEADS * NSPLIT];
__device__ float g_s[BATCH * HEADS * NSPLIT];
__device__ float g_acc[BATCH * HEADS * NSPLIT * HEADDIM];
__device__ unsigned int g_cnt[BATCH * HEADS];   // zero-init; reset by last CTA

__device__ __forceinline__ void cp_async16(void* smem_dst, const void* gmem_src)
{
    unsigned int s = (unsigned int)__cvta_generic_to_shared(smem_dst);
    asm volatile("cp.async.cg.shared.global [%0], [%1], 16;\n" :: "r"(s), "l"(gmem_src));
}
__device__ __forceinline__ void cp_commit()
{
    asm volatile("cp.async.commit_group;\n");
}
template <int N>
__device__ __forceinline__ void cp_wait()
{
    asm volatile("cp.async.wait_group %0;\n" :: "n"(N));
}

__global__ __launch_bounds__(NTHREADS, 6)
void paged_attn_split_kernel(const float* __restrict__ query,
                             const float* __restrict__ key_cache,
                             const float* __restrict__ value_cache,
                             const int*   __restrict__ block_tables,
                             const int*   __restrict__ context_lens,
                             float*       __restrict__ out)
{
    const int h     = blockIdx.x;
    const int b     = blockIdx.y;
    const int split = blockIdx.z;
    const int tid   = threadIdx.x;
    const int lane  = tid & 31;
    const int warp  = tid >> 5;

    const int bh    = b * HEADS + h;
    const int ctx   = context_lens[b];
    const int start = split * CHUNK;

    // Inactive split: exit immediately — no partial write, no fence, no atomic.
    // The ticket below counts only the n_active CTAs of this (b,h).
    if (start >= ctx) return;

    const int n_active = (ctx + CHUNK - 1) / CHUNK;   // 1..NSPLIT
    const int p        = bh * NSPLIT + split;
    const int end      = min(start + CHUNK, ctx);
    const int nst      = (end - start + TPS - 1) / TPS;   // #stages (1..4)

    __shared__ float s_k[NSTAGE][TPS][HEADDIM];       // 16 KB
    __shared__ float s_v[NSTAGE][TPS][HEADDIM];       // 16 KB
    __shared__ float s_acc[NWARPS * HEADDIM];         // 4 KB
    __shared__ int   s_btab[CHUNK / BLOCK_SIZE];      // 4 entries
    __shared__ float s_wm[NWARPS], s_ws[NWARPS];
    __shared__ unsigned int s_ticket;

    if (tid < CHUNK / BLOCK_SIZE)
        s_btab[tid] = block_tables[b * MAX_BLOCKS + (start >> 4) + tid];
    __syncthreads();

    const float4 q4 =
        reinterpret_cast<const float4*>(query + (size_t)bh * HEADDIM)[lane];

    // ---- Hoisted per-thread fill constants --------------------------------
    // Stage == one KV block: block index uniform (s_btab[st]); each thread
    // covers two 16B slots (tokens tokA=warp, tokB=warp+8) at fixed offsets.
    const int    tokA  = tid >> 5;              // 0..7
    const int    tokB  = tokA + 8;              // 8..15
    const int    part4 = (tid & 31) * 4;        // float offset of 16B unit
    const size_t cA = ((size_t)tokA * HEADS + h) * HEADDIM + part4;
    const size_t cB = ((size_t)tokB * HEADS + h) * HEADDIM + part4;

    auto issue_stage = [&](int st) {
        const int    buf  = st & 1;
        const int    base = start + st * TPS;
        const size_t bb   = (size_t)s_btab[st] * BLOCK_ELEMS;  // uniform LDS
        if (base + tokA < end) {
            cp_async16(&s_k[buf][tokA][part4], key_cache   + bb + cA);
            cp_async16(&s_v[buf][tokA][part4], value_cache + bb + cA);
        } else {
            *reinterpret_cast<float4*>(&s_v[buf][tokA][part4]) =
                make_float4(0.f, 0.f, 0.f, 0.f);
        }
        if (base + tokB < end) {
            cp_async16(&s_k[buf][tokB][part4], key_cache   + bb + cB);
            cp_async16(&s_v[buf][tokB][part4], value_cache + bb + cB);
        } else {
            *reinterpret_cast<float4*>(&s_v[buf][tokB][part4]) =
                make_float4(0.f, 0.f, 0.f, 0.f);
        }
    };

    float m = NEG_BIG, s = 0.0f;
    float4 acc = make_float4(0.f, 0.f, 0.f, 0.f);

    issue_stage(0);
    cp_commit();

    for (int st = 0; st < nst; st++) {
        if (st + 1 < nst) {
            issue_stage(st + 1);
            cp_commit();
            cp_wait<1>();          // stage st complete, st+1 may be pending
        } else {
            cp_wait<0>();
        }
        __syncthreads();

        const int buf  = st & 1;
        const int t0   = start + st * TPS + warp * 2;
        const int t1   = t0 + 1;
        const int tok0 = warp * 2, tok1 = tok0 + 1;

        const float4 k0 = reinterpret_cast<const float4*>(s_k[buf][tok0])[lane];
        const float4 k1 = reinterpret_cast<const float4*>(s_k[buf][tok1])[lane];
        const float4 v0 = reinterpret_cast<const float4*>(s_v[buf][tok0])[lane];
        const float4 v1 = reinterpret_cast<const float4*>(s_v[buf][tok1])[lane];

        float d0 = k0.x * q4.x + k0.y * q4.y + k0.z * q4.z + k0.w * q4.w;
        float d1 = k1.x * q4.x + k1.y * q4.y + k1.z * q4.z + k1.w * q4.w;
        #pragma unroll
        for (int o2 = 16; o2; o2 >>= 1) {
            d0 += __shfl_xor_sync(0xFFFFFFFFu, d0, o2);
            d1 += __shfl_xor_sync(0xFFFFFFFFu, d1, o2);
        }
        // Finite sentinel: select kills NaN from uninit tail smem; no inf-inf.
        d0 = (t0 < end) ? d0 * SCALE : NEG_BIG;
        d1 = (t1 < end) ? d1 * SCALE : NEG_BIG;

        const float mnew = fmaxf(m, fmaxf(d0, d1));
        // Fully-idle warp: mnew==NEG_BIG, resc=p=1, but V is zeroed and the
        // merge weight exp(NEG_BIG - gm) underflows to 0 -> contributes nothing.
        const float resc = __expf(m - mnew);
        const float p0   = __expf(d0 - mnew);
        const float p1   = __expf(d1 - mnew);
        s = s * resc + p0 + p1;
        acc.x = acc.x * resc + p0 * v0.x + p1 * v1.x;
        acc.y = acc.y * resc + p0 * v0.y + p1 * v1.y;
        acc.z = acc.z * resc + p0 * v0.z + p1 * v1.z;
        acc.w = acc.w * resc + p0 * v0.w + p1 * v1.w;
        m = mnew;

        __syncthreads();           // all reads done before buffer reuse
    }

    // ---- Merge warp partials -> split partial ----
    if (lane == 0) { s_wm[warp] = m; s_ws[warp] = s; }
    reinterpret_cast<float4*>(&s_acc[warp * HEADDIM])[lane] = acc;
    __syncthreads();

    if (tid < HEADDIM) {
        float gm = NEG_BIG;
        #pragma unroll
        for (int w = 0; w < NWARPS; w++) gm = fmaxf(gm, s_wm[w]);
        float S = 0.0f, A = 0.0f;
        #pragma unroll
        for (int w = 0; w < NWARPS; w++) {
            const float wt = __expf(s_wm[w] - gm);   // idle warp: underflow -> 0
            S += wt * s_ws[w];
            A += wt * s_acc[w * HEADDIM + tid];
        }
        g_acc[(size_t)p * HEADDIM + tid] = A;
        if (tid == 0) { g_m[p] = gm; g_s[p] = S; }
    }

    // ---- Arrival ticket: last ACTIVE CTA of this (b,h) merges its splits ----
    if (tid < HEADDIM) __threadfence();   // order partial writes (writers only)
    __syncthreads();
    if (tid == 0) s_ticket = atomicAdd(&g_cnt[bh], 1u);
    __syncthreads();

    if (s_ticket == (unsigned)(n_active - 1)) {
        __threadfence();    // acquire peers' partials
        if (tid < HEADDIM) {
            float gm = NEG_BIG;
            for (int i = 0; i < n_active; i++)
                gm = fmaxf(gm, g_m[bh * NSPLIT + i]);
            float S = 0.0f, A = 0.0f;
            for (int i = 0; i < n_active; i++) {
                const float wt = __expf(g_m[bh * NSPLIT + i] - gm);
                S += wt * g_s[bh * NSPLIT + i];
                A += wt * g_acc[((size_t)bh * NSPLIT + i) * HEADDIM + tid];
            }
            out[(size_t)bh * HEADDIM + tid] = A / S;
        }
        if (tid == 0) g_cnt[bh] = 0u;   // reset for next graph replay
    }
}

extern "C" void kernel_launch(void* const* d_in, const int* in_sizes, int n_in,
                              void* d_out, int out_size)
{
    const float* query        = (const float*)d_in[0];
    const float* key_cache    = (const float*)d_in[1];
    const float* value_cache  = (const float*)d_in[2];
    const int*   block_tables = (const int*)d_in[3];
    const int*   context_lens = (const int*)d_in[4];
    float*       out          = (float*)d_out;

    dim3 grid(HEADS, BATCH, NSPLIT);
    paged_attn_split_kernel<<<grid, NTHREADS>>>(query, key_cache, value_cache,
                                                block_tables, context_lens, out);
}

// round 17
// speedup vs baseline: 1.0534x; 1.0497x over previous
#include <cuda_runtime.h>
#include <cuda_bf16.h>
#include <math.h>

#define BATCH       32
#define HEADS       16
#define HEADDIM     128
#define BLOCK_SIZE  16
#define MAX_BLOCKS  128
#define MAX_CTX     (MAX_BLOCKS * BLOCK_SIZE)   // 2048
#define SCALE       (0.08838834764831845f)      // 1/sqrt(128)
#define NEG_BIG     (-1e30f)                    // finite -inf stand-in (no NaN arith)

#define NSPLIT      16
#define CHUNK       (MAX_CTX / NSPLIT)          // 128 tokens per split
#define NWARPS      8
#define NTHREADS    (NWARPS * 32)               // 256
#define TPS         16                          // tokens per stage == one KV block
#define NSTAGE      2                           // double buffer
#define BLOCK_ELEMS ((size_t)BLOCK_SIZE * HEADS * HEADDIM)   // floats per KV block

// Split-KV partial results: per (b, h, split)
__device__ float g_m[BATCH * HEADS * NSPLIT];
__device__ float g_s[BATCH * HEADS * NSPLIT];
__device__ float g_acc[BATCH * HEADS * NSPLIT * HEADDIM];
__device__ unsigned int g_cnt[BATCH * HEADS];   // zero-init; reset by last CTA

__device__ __forceinline__ void cp_async16(void* smem_dst, const void* gmem_src)
{
    unsigned int s = (unsigned int)__cvta_generic_to_shared(smem_dst);
    asm volatile("cp.async.cg.shared.global [%0], [%1], 16;\n" :: "r"(s), "l"(gmem_src));
}
__device__ __forceinline__ void cp_commit()
{
    asm volatile("cp.async.commit_group;\n");
}
template <int N>
__device__ __forceinline__ void cp_wait()
{
    asm volatile("cp.async.wait_group %0;\n" :: "n"(N));
}

// Release+acquire ticket: RMW on a single address forms a release chain; the
// last arriver's acquire makes ALL earlier CTAs' pre-barrier stores visible.
// Replaces per-thread __threadfence (4x MEMBAR.GPU/CTA) + merger fence.
__device__ __forceinline__ unsigned int ticket_acq_rel(unsigned int* addr)
{
    unsigned int old;
    asm volatile("atom.add.acq_rel.gpu.global.u32 %0, [%1], 1;"
                 : "=r"(old) : "l"(addr) : "memory");
    return old;
}

__global__ __launch_bounds__(NTHREADS, 6)
void paged_attn_split_kernel(const float* __restrict__ query,
                             const float* __restrict__ key_cache,
                             const float* __restrict__ value_cache,
                             const int*   __restrict__ block_tables,
                             const int*   __restrict__ context_lens,
                             float*       __restrict__ out)
{
    const int h     = blockIdx.x;
    const int b     = blockIdx.y;
    const int split = blockIdx.z;
    const int tid   = threadIdx.x;
    const int lane  = tid & 31;
    const int warp  = tid >> 5;

    const int bh    = b * HEADS + h;
    const int ctx   = context_lens[b];
    const int start = split * CHUNK;

    // Inactive split: exit immediately — no partial write, no fence, no atomic.
    // The ticket below counts only the n_active CTAs of this (b,h).
    if (start >= ctx) return;

    const int n_active = (ctx + CHUNK - 1) / CHUNK;   // 1..NSPLIT
    const int p        = bh * NSPLIT + split;
    const int end      = min(start + CHUNK, ctx);
    const int nst      = (end - start + TPS - 1) / TPS;   // #stages (1..8)

    __shared__ float s_k[NSTAGE][TPS][HEADDIM];       // 16 KB
    __shared__ float s_v[NSTAGE][TPS][HEADDIM];       // 16 KB
    __shared__ float s_acc[NWARPS * HEADDIM];         // 4 KB
    __shared__ int   s_btab[CHUNK / BLOCK_SIZE];      // 8 entries
    __shared__ float s_wm[NWARPS], s_ws[NWARPS];
    __shared__ unsigned int s_ticket;

    if (tid < CHUNK / BLOCK_SIZE)
        s_btab[tid] = block_tables[b * MAX_BLOCKS + (start >> 4) + tid];
    __syncthreads();

    const float4 q4 =
        reinterpret_cast<const float4*>(query + (size_t)bh * HEADDIM)[lane];

    // ---- Hoisted per-thread fill constants --------------------------------
    // Stage == one KV block: block index uniform (s_btab[st]); each thread
    // covers two 16B slots (tokens tokA=warp, tokB=warp+8) at fixed offsets.
    const int    tokA  = tid >> 5;              // 0..7
    const int    tokB  = tokA + 8;              // 8..15
    const int    part4 = (tid & 31) * 4;        // float offset of 16B unit
    const size_t cA = ((size_t)tokA * HEADS + h) * HEADDIM + part4;
    const size_t cB = ((size_t)tokB * HEADS + h) * HEADDIM + part4;

    auto issue_stage = [&](int st) {
        const int    buf  = st & 1;
        const int    base = start + st * TPS;
        const size_t bb   = (size_t)s_btab[st] * BLOCK_ELEMS;  // uniform LDS
        if (base + tokA < end) {
            cp_async16(&s_k[buf][tokA][part4], key_cache   + bb + cA);
            cp_async16(&s_v[buf][tokA][part4], value_cache + bb + cA);
        } else {
            *reinterpret_cast<float4*>(&s_v[buf][tokA][part4]) =
                make_float4(0.f, 0.f, 0.f, 0.f);
        }
        if (base + tokB < end) {
            cp_async16(&s_k[buf][tokB][part4], key_cache   + bb + cB);
            cp_async16(&s_v[buf][tokB][part4], value_cache + bb + cB);
        } else {
            *reinterpret_cast<float4*>(&s_v[buf][tokB][part4]) =
                make_float4(0.f, 0.f, 0.f, 0.f);
        }
    };

    float m = NEG_BIG, s = 0.0f;
    float4 acc = make_float4(0.f, 0.f, 0.f, 0.f);

    issue_stage(0);
    cp_commit();

    for (int st = 0; st < nst; st++) {
        if (st + 1 < nst) {
            issue_stage(st + 1);
            cp_commit();
            cp_wait<1>();          // stage st complete, st+1 may be pending
        } else {
            cp_wait<0>();
        }
        __syncthreads();

        const int buf  = st & 1;
        const int t0   = start + st * TPS + warp * 2;
        const int t1   = t0 + 1;
        const int tok0 = warp * 2, tok1 = tok0 + 1;

        const float4 k0 = reinterpret_cast<const float4*>(s_k[buf][tok0])[lane];
        const float4 k1 = reinterpret_cast<const float4*>(s_k[buf][tok1])[lane];
        const float4 v0 = reinterpret_cast<const float4*>(s_v[buf][tok0])[lane];
        const float4 v1 = reinterpret_cast<const float4*>(s_v[buf][tok1])[lane];

        float d0 = k0.x * q4.x + k0.y * q4.y + k0.z * q4.z + k0.w * q4.w;
        float d1 = k1.x * q4.x + k1.y * q4.y + k1.z * q4.z + k1.w * q4.w;
        #pragma unroll
        for (int o2 = 16; o2; o2 >>= 1) {
            d0 += __shfl_xor_sync(0xFFFFFFFFu, d0, o2);
            d1 += __shfl_xor_sync(0xFFFFFFFFu, d1, o2);
        }
        // Finite sentinel: select kills NaN from uninit tail smem; no inf-inf.
        d0 = (t0 < end) ? d0 * SCALE : NEG_BIG;
        d1 = (t1 < end) ? d1 * SCALE : NEG_BIG;

        const float mnew = fmaxf(m, fmaxf(d0, d1));
        // Fully-idle warp: mnew==NEG_BIG, resc=p=1, but V is zeroed and the
        // merge weight exp(NEG_BIG - gm) underflows to 0 -> contributes nothing.
        const float resc = __expf(m - mnew);
        const float p0   = __expf(d0 - mnew);
        const float p1   = __expf(d1 - mnew);
        s = s * resc + p0 + p1;
        acc.x = acc.x * resc + p0 * v0.x + p1 * v1.x;
        acc.y = acc.y * resc + p0 * v0.y + p1 * v1.y;
        acc.z = acc.z * resc + p0 * v0.z + p1 * v1.z;
        acc.w = acc.w * resc + p0 * v0.w + p1 * v1.w;
        m = mnew;

        __syncthreads();           // all reads done before buffer reuse
    }

    // ---- Merge warp partials -> split partial ----
    if (lane == 0) { s_wm[warp] = m; s_ws[warp] = s; }
    reinterpret_cast<float4*>(&s_acc[warp * HEADDIM])[lane] = acc;
    __syncthreads();

    if (tid < HEADDIM) {
        float gm = NEG_BIG;
        #pragma unroll
        for (int w = 0; w < NWARPS; w++) gm = fmaxf(gm, s_wm[w]);
        float S = 0.0f, A = 0.0f;
        #pragma unroll
        for (int w = 0; w < NWARPS; w++) {
            const float wt = __expf(s_wm[w] - gm);   // idle warp: underflow -> 0
            S += wt * s_ws[w];
            A += wt * s_acc[w * HEADDIM + tid];
        }
        g_acc[(size_t)p * HEADDIM + tid] = A;
        if (tid == 0) { g_m[p] = gm; g_s[p] = S; }
    }

    // ---- Arrival ticket (release-chain): last ACTIVE CTA merges its splits --
    // __syncthreads gives happens-before from all writers to tid0's RMW; the
    // .acq_rel RMW chain on g_cnt[bh] publishes/acquires all partials. No
    // MEMBAR.GPU per thread needed.
    __syncthreads();
    if (tid == 0) s_ticket = ticket_acq_rel(&g_cnt[bh]);
    __syncthreads();

    if (s_ticket == (unsigned)(n_active - 1)) {
        if (tid < HEADDIM) {
            float gm = NEG_BIG;
            for (int i = 0; i < n_active; i++)
                gm = fmaxf(gm, g_m[bh * NSPLIT + i]);
            float S = 0.0f, A = 0.0f;
            for (int i = 0; i < n_active; i++) {
                const float wt = __expf(g_m[bh * NSPLIT + i] - gm);
                S += wt * g_s[bh * NSPLIT + i];
                A += wt * g_acc[((size_t)bh * NSPLIT + i) * HEADDIM + tid];
            }
            out[(size_t)bh * HEADDIM + tid] = A / S;
        }
        if (tid == 0) g_cnt[bh] = 0u;   // reset for next graph replay
    }
}

extern "C" void kernel_launch(void* const* d_in, const int* in_sizes, int n_in,
                              void* d_out, int out_size)
{
    const float* query        = (const float*)d_in[0];
    const float* key_cache    = (const float*)d_in[1];
    const float* value_cache  = (const float*)d_in[2];
    const int*   block_tables = (const int*)d_in[3];
    const int*   context_lens = (const int*)d_in[4];
    float*       out          = (float*)d_out;

    dim3 grid(HEADS, BATCH, NSPLIT);
    paged_attn_split_kernel<<<grid, NTHREADS>>>(query, key_cache, value_cache,
                                                block_tables, context_lens, out);
}